// round 7
// baseline (speedup 1.0000x reference)
#include <cuda_runtime.h>
#include <cstdint>
#include <cstddef>

#define NN 8192
#define RWD 10
#define HD1 100
#define HD2 100
#define NB_SEG 256

#define MSPLIT 16
#define MW 64                       // m-window per stage
#define ROWSB 128                   // rows per block (32 lanes x 4)
#define ITERS ((NN / MSPLIT) / MW)  // 8
#define HOP_TILE_BYTES (ROWSB * MW * 4)   // 32768
#define X_TILE_BYTES (MW * RWD * 4)       // 2560
#define SMEM_A_BYTES (3 * (HOP_TILE_BYTES + X_TILE_BYTES))  // 105984 -> 2 blocks/SM

typedef unsigned long long u64;

// ---------------- scratch (static device arrays; no allocation) ----------------
__device__ float g_part[3 * MSPLIT * NN * RWD];  // per-m-split partials of hopX (15.7MB)

// ---------------- helpers ----------------
__device__ __forceinline__ void fma2(u64 &acc, u64 a, u64 b) {
    asm("fma.rn.f32x2 %0, %1, %2, %0;" : "+l"(acc) : "l"(a), "l"(b));
}
__device__ __forceinline__ u64 pack2(float x, float y) {
    u64 r; asm("mov.b64 %0, {%1, %2};" : "=l"(r) : "f"(x), "f"(y)); return r;
}
__device__ __forceinline__ float2 unpack2(u64 v) {
    float2 r; asm("mov.b64 {%0, %1}, %2;" : "=f"(r.x), "=f"(r.y) : "l"(v)); return r;
}
__device__ __forceinline__ void cp_async16(uint32_t dst, const void* src) {
    asm volatile("cp.async.cg.shared.global [%0], [%1], 16;" :: "r"(dst), "l"(src));
}
__device__ __forceinline__ void cp_commit() { asm volatile("cp.async.commit_group;"); }
template<int N> __device__ __forceinline__ void cp_wait() {
    asm volatile("cp.async.wait_group %0;" :: "n"(N));
}

// =====================================================================
// Kernel A: partial hopX over this block's m-range (512 m of one hop).
// 256 thr / 8 warps, 128 rows. Warp w owns m-columns c4 in {2w, 2w+1}
// of each 64-m window; lane l accumulates rows {l, l+32, l+64, l+96}.
// Triple-buffered cp.async, 2 blocks resident per SM for stall overlap.
// =====================================================================
extern "C" __global__ void __launch_bounds__(256, 2)
hop_gemv_kernel(const float* __restrict__ hop0, const float* __restrict__ hop1,
                const float* __restrict__ hop2, const float* __restrict__ X)
{
    extern __shared__ char smem[];
    char* hop_s = smem;                                   // 3 x 32KB
    char* x_s   = smem + 3 * HOP_TILE_BYTES;              // 3 x 2.5KB

    const int b   = blockIdx.x;                  // 3072 blocks
    const int k   = b >> 10;                     // 0..2
    const int rem = b & 1023;
    const int rg  = rem >> 4;                    // row group 0..63
    const int sp  = rem & 15;                    // m split 0..15
    const int row0   = rg * ROWSB;
    const int m_base = sp * (NN / MSPLIT);
    const float* hop = (k == 0) ? hop0 : (k == 1) ? hop1 : hop2;

    const int t = threadIdx.x;
    const int w = t >> 5, l = t & 31;

    // per-thread cp.async bases (stage deltas become immediates)
    const int tr = t >> 4;                    // 0..15 (row-within-16)
    const int tc = t & 15;                    // float4 column 0..15
    const int slotS = tc ^ (tr & 7);          // store slot: constant per thread
    const char* gsrc0 = (const char*)(hop + (size_t)(row0 + tr) * NN + m_base + tc * 4);
    const uint32_t hdst0 = (uint32_t)__cvta_generic_to_shared(hop_s)
                         + (uint32_t)((tr * 16 + slotS) * 16);
    const char* xsrc0 = (const char*)(X + (size_t)m_base * RWD);
    const uint32_t xdst0 = (uint32_t)__cvta_generic_to_shared(x_s) + (uint32_t)(t * 16);

    auto stage = [&](int buf, int it) {
        const char* gs = gsrc0 + (size_t)it * (MW * 4);
        uint32_t hd = hdst0 + buf * HOP_TILE_BYTES;
        #pragma unroll
        for (int i = 0; i < 8; i++)
            cp_async16(hd + i * 4096, gs + (size_t)i * (16 * NN * 4));
        if (t < 160)
            cp_async16(xdst0 + buf * X_TILE_BYTES, xsrc0 + (size_t)it * X_TILE_BYTES + t * 16);
        cp_commit();
    };

    u64 acc[4][5];
    #pragma unroll
    for (int g = 0; g < 4; g++)
        #pragma unroll
        for (int p = 0; p < 5; p++) acc[g][p] = 0ull;

    stage(0, 0);
    stage(1, 1);

    int bc = 2;                                  // buffer cursor for stage(it+2)
    #pragma unroll 1
    for (int it = 0; it < ITERS; it++) {
        __syncthreads();                    // compute(it-1) done -> buffer free
        if (it + 2 < ITERS) {
            stage(bc, it + 2);
            bc = (bc == 2) ? 0 : bc + 1;
            cp_wait<2>();
        } else if (it + 1 < ITERS) cp_wait<1>();
        else                       cp_wait<0>();
        __syncthreads();                    // buffer it visible to all warps

        const float4* hb = (const float4*)(hop_s + (it % 3) * HOP_TILE_BYTES);
        const u64*    xb = (const u64*)(x_s + (it % 3) * X_TILE_BYTES);

        #pragma unroll
        for (int q = 0; q < 2; q++) {
            const int c4   = (w << 1) + q;          // 0..15
            const int slot = c4 ^ (l & 7);
            float4 h4[4];
            #pragma unroll
            for (int g = 0; g < 4; g++)
                h4[g] = hb[((l + (g << 5)) << 4) + slot];
            const u64* xp = xb + c4 * 20;           // 4 m's x 5 u64 (d-pairs)
            #pragma unroll
            for (int j = 0; j < 4; j++) {
                const float* hv0 = (const float*)&h4[0];
                const float* hv1 = (const float*)&h4[1];
                const float* hv2 = (const float*)&h4[2];
                const float* hv3 = (const float*)&h4[3];
                u64 A0 = pack2(hv0[j], hv0[j]);
                u64 A1 = pack2(hv1[j], hv1[j]);
                u64 A2 = pack2(hv2[j], hv2[j]);
                u64 A3 = pack2(hv3[j], hv3[j]);
                #pragma unroll
                for (int p = 0; p < 5; p++) {
                    u64 xv = xp[j * 5 + p];
                    fma2(acc[0][p], A0, xv);
                    fma2(acc[1][p], A1, xv);
                    fma2(acc[2][p], A2, xv);
                    fma2(acc[3][p], A3, xv);
                }
            }
        }
    }

    // cross-warp reduction (warps covered disjoint m-subslices)
    float* red = (float*)smem;              // alias buffers (free now): 40KB needed
    __syncthreads();
    #pragma unroll
    for (int g = 0; g < 4; g++) {
        int row = l + (g << 5);
        #pragma unroll
        for (int p = 0; p < 5; p++) {
            float2 v = unpack2(acc[g][p]);
            red[(w * ROWSB + row) * RWD + 2 * p]     = v.x;
            red[(w * ROWSB + row) * RWD + 2 * p + 1] = v.y;
        }
    }
    __syncthreads();
    for (int f = t; f < ROWSB * RWD; f += 256) {
        int row = f / RWD, d = f % RWD;
        float s = 0.f;
        #pragma unroll
        for (int ww = 0; ww < 8; ww++) s += red[(ww * ROWSB + row) * RWD + d];
        g_part[((size_t)(k * MSPLIT + sp) * NN + row0 + row) * RWD + d] = s;
    }
}

// =====================================================================
// Kernel B (fused MLP + segment pool): block b = segment b.
// Binary search sorted batch_idx for [lo,hi); process nodes in tiles of 32
// with the register-tiled MLP; mask inactive rows at the reduction; sum the
// segment via width-16 shfl + smem accumulator (deterministic order).
// =====================================================================
#define SMEM_B_BYTES ((112*100 + 32*100 + 100*12 + 320 + 100 + 100 + 112) * 4)

__device__ __forceinline__ int lbound(const int* a, int n, int v) {
    int lo = 0, hi = n;
    while (lo < hi) { int mid = (lo + hi) >> 1; if (a[mid] < v) lo = mid + 1; else hi = mid; }
    return lo;
}

extern "C" __global__ void __launch_bounds__(256)
mlp_pool_kernel(const float* __restrict__ X, const float* __restrict__ W1,
                const float* __restrict__ b1, const float* __restrict__ W2,
                const float* __restrict__ b2, const int* __restrict__ bidx,
                float* __restrict__ out)
{
    extern __shared__ char smemb[];
    float* w2t = (float*)smemb;             // [112][100]  (rows 100..111 zero)
    float* hsm = w2t + 112 * 100;           // [32][100]
    float* w1t = hsm + 32 * 100;            // [100][12]
    float* inp = w1t + 100 * 12;            // [320]
    float* b1s = inp + 320;                 // [100]
    float* b2s = b1s + 100;                 // [100]
    float* seg = b2s + 100;                 // [112] segment accumulator

    const int t = threadIdx.x;
    const int bs = blockIdx.x;              // segment id

    const int lo = lbound(bidx, NN, bs);
    const int hi = lbound(bidx, NN, bs + 1);

    if (t < 112) seg[t] = 0.0f;
    if (t < 100) b2s[t] = b2[t] + b2[100 + t] + b2[200 + t] + b2[300 + t];
    for (int f = t; f < 12 * 100; f += 256) w2t[100 * 100 + f] = 0.0f;  // stays zero

    const int r0  = t & 15;           // local node row base
    const int obi = t >> 4;           // 0..15
    const int ob  = obi * 7;          // output base (16 tiles x 7 = 112)

    for (int tile0 = lo; tile0 < hi; tile0 += 32) {
        int nt = hi - tile0; if (nt > 32) nt = 32;

        u64 acc[2][7];
        #pragma unroll
        for (int g = 0; g < 2; g++)
            #pragma unroll
            for (int o = 0; o < 7; o++) acc[g][o] = 0ull;

        for (int k = 0; k < 4; k++) {
            __syncthreads();   // previous phase-2 / previous tile done
            for (int f = t; f < 10000; f += 256) {
                int d = f / 100, o = f % 100;
                w2t[o * 100 + d] = W2[k * 10000 + f];     // transpose: [o][d]
            }
            for (int f = t; f < 1000; f += 256) {
                int r = f / 100, j = f % 100;
                w1t[j * 12 + r] = W1[k * 1000 + f];       // transpose: [j][r]
            }
            if (t < 100) b1s[t] = b1[k * 100 + t];
            // input tile (zero-fill inactive rows; masked again at reduction)
            for (int f = t; f < 320; f += 256) {
                float v = 0.0f;
                if (f < nt * RWD) {
                    if (k == 0) v = X[(size_t)tile0 * RWD + f];
                    else {
                        const float* base = g_part
                            + ((size_t)(k - 1) * MSPLIT * NN + tile0) * RWD;
                        float s = 0.f;
                        #pragma unroll
                        for (int sp = 0; sp < MSPLIT; sp++)
                            s += base[(size_t)sp * NN * RWD + f];
                        v = s;
                    }
                }
                inp[f] = v;
            }
            __syncthreads();

            // phase 1: hsm[i][j] = relu(b1 + inp[i].W1[:,j])
            {
                const int i = t >> 3, jq = t & 7;
                float xr[10];
                #pragma unroll
                for (int r = 0; r < 10; r++) xr[r] = inp[i * 10 + r];
                #pragma unroll
                for (int jj = 0; jj < 13; jj++) {
                    int j = jq * 13 + jj;
                    if (j < 100) {
                        float s = b1s[j];
                        #pragma unroll
                        for (int r = 0; r < 10; r++) s = fmaf(xr[r], w1t[j * 12 + r], s);
                        hsm[i * 100 + j] = fmaxf(s, 0.0f);
                    }
                }
            }
            __syncthreads();

            // phase 2: acc[g][oo] += hsm[row].w2t[o] over d (f32x2 pairs)
            #pragma unroll 5
            for (int d4 = 0; d4 < 25; d4++) {
                ulonglong2 h[2];
                #pragma unroll
                for (int g = 0; g < 2; g++)
                    h[g] = *(const ulonglong2*)&hsm[(r0 + 16 * g) * 100 + d4 * 4];
                #pragma unroll
                for (int oo = 0; oo < 7; oo++) {
                    ulonglong2 wv = *(const ulonglong2*)&w2t[(ob + oo) * 100 + d4 * 4];
                    #pragma unroll
                    for (int g = 0; g < 2; g++) {
                        fma2(acc[g][oo], h[g].x, wv.x);
                        fma2(acc[g][oo], h[g].y, wv.y);
                    }
                }
            }
        }

        // reduce this tile into the segment accumulator (mask inactive rows)
        float c[7];
        #pragma unroll
        for (int oo = 0; oo < 7; oo++) {
            float2 v0 = unpack2(acc[0][oo]);
            float2 v1 = unpack2(acc[1][oo]);
            float s = 0.0f;
            if (r0 < nt)      s += v0.x + v0.y;
            if (r0 + 16 < nt) s += v1.x + v1.y;
            c[oo] = s;
        }
        #pragma unroll
        for (int off = 8; off > 0; off >>= 1)
            #pragma unroll
            for (int oo = 0; oo < 7; oo++)
                c[oo] += __shfl_down_sync(0xffffffffu, c[oo], off, 16);
        if (r0 == 0) {
            #pragma unroll
            for (int oo = 0; oo < 7; oo++) seg[ob + oo] += c[oo];
        }
        // next tile's first __syncthreads orders seg writes vs. reads
    }

    __syncthreads();
    if (t < 100)
        out[bs * 100 + t] = seg[t] + (float)(hi - lo) * b2s[t];
}

// =====================================================================
extern "C" void kernel_launch(void* const* d_in, const int* in_sizes, int n_in,
                              void* d_out, int out_size)
{
    const float* X    = (const float*)d_in[0];   // walk_feats (8192,10)
    const float* hop1 = (const float*)d_in[1];
    const float* hop2 = (const float*)d_in[2];
    const float* hop3 = (const float*)d_in[3];
    const int*   bidx = (const int*)d_in[4];
    const float* W1   = (const float*)d_in[5];   // (4,10,100)
    const float* b1   = (const float*)d_in[6];   // (4,100)
    const float* W2   = (const float*)d_in[7];   // (4,100,100)
    const float* b2   = (const float*)d_in[8];   // (4,100)
    float* out = (float*)d_out;                  // (256,100)

    (void)in_sizes; (void)n_in; (void)out_size;

    cudaFuncSetAttribute(hop_gemv_kernel, cudaFuncAttributeMaxDynamicSharedMemorySize, SMEM_A_BYTES);
    cudaFuncSetAttribute(mlp_pool_kernel, cudaFuncAttributeMaxDynamicSharedMemorySize, SMEM_B_BYTES);

    hop_gemv_kernel<<<3072, 256, SMEM_A_BYTES>>>(hop1, hop2, hop3, X);
    mlp_pool_kernel<<<NB_SEG, 256, SMEM_B_BYTES>>>(X, W1, b1, W2, b2, bidx, out);
}

// round 8
// speedup vs baseline: 1.2075x; 1.2075x over previous
#include <cuda_runtime.h>
#include <cstdint>
#include <cstddef>

#define NN 8192
#define RWD 10
#define HD1 100
#define HD2 100
#define NB_SEG 256

#define MSPLIT 16
#define MW 64                       // m-window per stage
#define ROWSB 128                   // rows per block (32 lanes x 4)
#define ITERS ((NN / MSPLIT) / MW)  // 8
#define HOP_TILE_BYTES (ROWSB * MW * 4)   // 32768
#define X_TILE_BYTES (MW * RWD * 4)       // 2560
#define SMEM_A_BYTES (3 * (HOP_TILE_BYTES + X_TILE_BYTES))  // 105984 -> 2 blocks/SM

typedef unsigned long long u64;

// ---------------- scratch (static device arrays; no allocation) ----------------
__device__ float g_part[3 * MSPLIT * NN * RWD];  // per-m-split partials of hopX
__device__ float g_nodeout[NN * HD2];            // per-node summed MLP output

// ---------------- helpers ----------------
__device__ __forceinline__ void fma2(u64 &acc, u64 a, u64 b) {
    asm("fma.rn.f32x2 %0, %1, %2, %0;" : "+l"(acc) : "l"(a), "l"(b));
}
__device__ __forceinline__ u64 pack2(float x, float y) {
    u64 r; asm("mov.b64 %0, {%1, %2};" : "=l"(r) : "f"(x), "f"(y)); return r;
}
__device__ __forceinline__ float2 unpack2(u64 v) {
    float2 r; asm("mov.b64 {%0, %1}, %2;" : "=f"(r.x), "=f"(r.y) : "l"(v)); return r;
}
__device__ __forceinline__ void cp_async16(uint32_t dst, const void* src) {
    asm volatile("cp.async.cg.shared.global [%0], [%1], 16;" :: "r"(dst), "l"(src));
}
__device__ __forceinline__ void cp_commit() { asm volatile("cp.async.commit_group;"); }
template<int N> __device__ __forceinline__ void cp_wait() {
    asm volatile("cp.async.wait_group %0;" :: "n"(N));
}

// =====================================================================
// Kernel A: partial hopX over this block's m-range (512 m of one hop).
// (unchanged from R7: 80.9% DRAM, protect the win)
// =====================================================================
extern "C" __global__ void __launch_bounds__(256, 2)
hop_gemv_kernel(const float* __restrict__ hop0, const float* __restrict__ hop1,
                const float* __restrict__ hop2, const float* __restrict__ X)
{
    extern __shared__ char smem[];
    char* hop_s = smem;                                   // 3 x 32KB
    char* x_s   = smem + 3 * HOP_TILE_BYTES;              // 3 x 2.5KB

    const int b   = blockIdx.x;                  // 3072 blocks
    const int k   = b >> 10;                     // 0..2
    const int rem = b & 1023;
    const int rg  = rem >> 4;                    // row group 0..63
    const int sp  = rem & 15;                    // m split 0..15
    const int row0   = rg * ROWSB;
    const int m_base = sp * (NN / MSPLIT);
    const float* hop = (k == 0) ? hop0 : (k == 1) ? hop1 : hop2;

    const int t = threadIdx.x;
    const int w = t >> 5, l = t & 31;

    const int tr = t >> 4;                    // 0..15
    const int tc = t & 15;                    // float4 column 0..15
    const int slotS = tc ^ (tr & 7);
    const char* gsrc0 = (const char*)(hop + (size_t)(row0 + tr) * NN + m_base + tc * 4);
    const uint32_t hdst0 = (uint32_t)__cvta_generic_to_shared(hop_s)
                         + (uint32_t)((tr * 16 + slotS) * 16);
    const char* xsrc0 = (const char*)(X + (size_t)m_base * RWD);
    const uint32_t xdst0 = (uint32_t)__cvta_generic_to_shared(x_s) + (uint32_t)(t * 16);

    auto stage = [&](int buf, int it) {
        const char* gs = gsrc0 + (size_t)it * (MW * 4);
        uint32_t hd = hdst0 + buf * HOP_TILE_BYTES;
        #pragma unroll
        for (int i = 0; i < 8; i++)
            cp_async16(hd + i * 4096, gs + (size_t)i * (16 * NN * 4));
        if (t < 160)
            cp_async16(xdst0 + buf * X_TILE_BYTES, xsrc0 + (size_t)it * X_TILE_BYTES + t * 16);
        cp_commit();
    };

    u64 acc[4][5];
    #pragma unroll
    for (int g = 0; g < 4; g++)
        #pragma unroll
        for (int p = 0; p < 5; p++) acc[g][p] = 0ull;

    stage(0, 0);
    stage(1, 1);

    int bc = 2;
    #pragma unroll 1
    for (int it = 0; it < ITERS; it++) {
        __syncthreads();
        if (it + 2 < ITERS) {
            stage(bc, it + 2);
            bc = (bc == 2) ? 0 : bc + 1;
            cp_wait<2>();
        } else if (it + 1 < ITERS) cp_wait<1>();
        else                       cp_wait<0>();
        __syncthreads();

        const float4* hb = (const float4*)(hop_s + (it % 3) * HOP_TILE_BYTES);
        const u64*    xb = (const u64*)(x_s + (it % 3) * X_TILE_BYTES);

        #pragma unroll
        for (int q = 0; q < 2; q++) {
            const int c4   = (w << 1) + q;          // 0..15
            const int slot = c4 ^ (l & 7);
            float4 h4[4];
            #pragma unroll
            for (int g = 0; g < 4; g++)
                h4[g] = hb[((l + (g << 5)) << 4) + slot];
            const u64* xp = xb + c4 * 20;
            #pragma unroll
            for (int j = 0; j < 4; j++) {
                const float* hv0 = (const float*)&h4[0];
                const float* hv1 = (const float*)&h4[1];
                const float* hv2 = (const float*)&h4[2];
                const float* hv3 = (const float*)&h4[3];
                u64 A0 = pack2(hv0[j], hv0[j]);
                u64 A1 = pack2(hv1[j], hv1[j]);
                u64 A2 = pack2(hv2[j], hv2[j]);
                u64 A3 = pack2(hv3[j], hv3[j]);
                #pragma unroll
                for (int p = 0; p < 5; p++) {
                    u64 xv = xp[j * 5 + p];
                    fma2(acc[0][p], A0, xv);
                    fma2(acc[1][p], A1, xv);
                    fma2(acc[2][p], A2, xv);
                    fma2(acc[3][p], A3, xv);
                }
            }
        }
    }

    float* red = (float*)smem;
    __syncthreads();
    #pragma unroll
    for (int g = 0; g < 4; g++) {
        int row = l + (g << 5);
        #pragma unroll
        for (int p = 0; p < 5; p++) {
            float2 v = unpack2(acc[g][p]);
            red[(w * ROWSB + row) * RWD + 2 * p]     = v.x;
            red[(w * ROWSB + row) * RWD + 2 * p + 1] = v.y;
        }
    }
    __syncthreads();
    for (int f = t; f < ROWSB * RWD; f += 256) {
        int row = f / RWD, d = f % RWD;
        float s = 0.f;
        #pragma unroll
        for (int ww = 0; ww < 8; ww++) s += red[(ww * ROWSB + row) * RWD + d];
        g_part[((size_t)(k * MSPLIT + sp) * NN + row0 + row) * RWD + d] = s;
    }
}

// =====================================================================
// Kernel B: node-parallel MLP, 256 blocks x 32 nodes.
// W2 kept in NATURAL [d][o] layout, cp.async double-buffered (no transpose,
// no STS conflicts, no int-div). Phase 1 stores h pre-duplicated as (h,h)
// u64 pairs. Phase 2: warp = 4 nodes, lane = o-quad (lanes 0..24 active),
// f32x2 pairs over adjacent o -> no horizontal add, STG.128 output.
// SMEM: w2[2]@0 (2x40000), hsm2@80000 (25600), inp@105600 (1280),
//       b2s@106880 (400). Total 107392 -> 2 blocks/SM.
// =====================================================================
#define W2S_BYTES 40000
#define SMEM_H_OFF   80000
#define SMEM_INP_OFF 105600
#define SMEM_B2_OFF  106880
#define SMEM_MLP_BYTES 107392

extern "C" __global__ void __launch_bounds__(256, 2)
mlp_kernel(const float* __restrict__ X, const float* __restrict__ W1,
           const float* __restrict__ b1, const float* __restrict__ W2,
           const float* __restrict__ b2)
{
    extern __shared__ char smemb[];
    u64*   hsm2 = (u64*)(smemb + SMEM_H_OFF);     // [32][100] (h,h) pairs
    float* inp  = (float*)(smemb + SMEM_INP_OFF); // [320]
    float* b2s  = (float*)(smemb + SMEM_B2_OFF);  // [100]

    const int t = threadIdx.x;
    const int w = t >> 5, l = t & 31;
    const int node0 = blockIdx.x * 32;

    const uint32_t w2base = (uint32_t)__cvta_generic_to_shared(smemb);

    auto stageW2 = [&](int buf, int k) {
        const float4* src = (const float4*)(W2 + k * 10000);  // 2500 x 16B
        uint32_t dst = w2base + buf * W2S_BYTES;
        #pragma unroll
        for (int i = 0; i < 9; i++)
            cp_async16(dst + (i * 256 + t) * 16, src + i * 256 + t);
        if (t < 196)
            cp_async16(dst + (2304 + t) * 16, src + 2304 + t);
        cp_commit();
    };

    if (t < 100) b2s[t] = b2[t] + b2[100 + t] + b2[200 + t] + b2[300 + t];

    stageW2(0, 0);
    stageW2(1, 1);

    u64 acc[4][2];
    #pragma unroll
    for (int nn = 0; nn < 4; nn++) { acc[nn][0] = 0ull; acc[nn][1] = 0ull; }

    #pragma unroll 1
    for (int k = 0; k < 4; k++) {
        // ---- input tile for this k (all warps past prev phase-2 sync) ----
        if (k == 0) {
            for (int f = t; f < 320; f += 256) inp[f] = X[(size_t)node0 * RWD + f];
        } else {
            const float* base = g_part + ((size_t)(k - 1) * MSPLIT * NN + node0) * RWD;
            for (int f = t; f < 320; f += 256) {
                float s = 0.f;
                #pragma unroll
                for (int sp = 0; sp < MSPLIT; sp++)
                    s += base[(size_t)sp * NN * RWD + f];
                inp[f] = s;
            }
        }
        if (k < 3) cp_wait<1>(); else cp_wait<0>();
        __syncthreads();   // weights(k) + inp visible; hsm2 free (prev phase2 done)

        // ---- phase 1: hsm2[i][j] = dup(relu(b1 + inp[i].W1[:,j])) ----
        {
            const int i = t >> 3, jg = t & 7;
            float xr[10];
            #pragma unroll
            for (int r = 0; r < 10; r++) xr[r] = inp[i * 10 + r];
            const float* w1k = W1 + k * 1000;
            const float* b1k = b1 + k * 100;
            #pragma unroll
            for (int jj = 0; jj < 13; jj++) {
                int j = jg * 13 + jj;
                if (j < 100) {
                    float s = __ldg(b1k + j);
                    #pragma unroll
                    for (int r = 0; r < 10; r++)
                        s = fmaf(xr[r], __ldg(w1k + r * 100 + j), s);
                    s = fmaxf(s, 0.0f);
                    hsm2[i * 100 + j] = pack2(s, s);
                }
            }
        }
        __syncthreads();

        // ---- phase 2: acc[nn][op] += h[node][d] * w2[d][o-pair] ----
        if (l < 25) {
            const float* w2f = (const float*)(smemb + (k & 1) * W2S_BYTES);
            #pragma unroll 5
            for (int d4 = 0; d4 < 25; d4++) {
                u64 wq[4][2];
                #pragma unroll
                for (int j = 0; j < 4; j++) {
                    ulonglong2 ww = *(const ulonglong2*)&w2f[(4 * d4 + j) * 100 + 4 * l];
                    wq[j][0] = ww.x; wq[j][1] = ww.y;
                }
                #pragma unroll
                for (int nn = 0; nn < 4; nn++) {
                    const int row = w * 4 + nn;
                    ulonglong2 h01 = *(const ulonglong2*)&hsm2[row * 100 + 4 * d4];
                    ulonglong2 h23 = *(const ulonglong2*)&hsm2[row * 100 + 4 * d4 + 2];
                    fma2(acc[nn][0], h01.x, wq[0][0]); fma2(acc[nn][1], h01.x, wq[0][1]);
                    fma2(acc[nn][0], h01.y, wq[1][0]); fma2(acc[nn][1], h01.y, wq[1][1]);
                    fma2(acc[nn][0], h23.x, wq[2][0]); fma2(acc[nn][1], h23.x, wq[2][1]);
                    fma2(acc[nn][0], h23.y, wq[3][0]); fma2(acc[nn][1], h23.y, wq[3][1]);
                }
            }
        }
        __syncthreads();   // w2 buffer (k&1) free for restage
        if (k + 2 < 4) stageW2(k & 1, k + 2);
    }

    // ---- output: node_out = acc + sum_k b2 ----
    if (l < 25) {
        float4 bv = *(const float4*)&b2s[4 * l];
        #pragma unroll
        for (int nn = 0; nn < 4; nn++) {
            int n = node0 + w * 4 + nn;
            float2 a0 = unpack2(acc[nn][0]);
            float2 a1 = unpack2(acc[nn][1]);
            float4 o4 = { a0.x + bv.x, a0.y + bv.y, a1.x + bv.z, a1.y + bv.w };
            *(float4*)&g_nodeout[(size_t)n * 100 + 4 * l] = o4;
        }
    }
}

// =====================================================================
// Kernel C: deterministic segment sum via binary search on sorted batch_idx
// =====================================================================
__device__ __forceinline__ int lbound(const int* a, int n, int v) {
    int lo = 0, hi = n;
    while (lo < hi) { int mid = (lo + hi) >> 1; if (a[mid] < v) lo = mid + 1; else hi = mid; }
    return lo;
}

extern "C" __global__ void segpool_kernel(const int* __restrict__ bidx,
                                          float* __restrict__ out)
{
    const int b = blockIdx.x;
    const int lo = lbound(bidx, NN, b);
    const int hi = lbound(bidx, NN, b + 1);
    const int t = threadIdx.x;
    if (t < 100) {
        float s = 0.f;
        int n = lo;
        for (; n + 3 < hi; n += 4) {
            s += g_nodeout[(size_t)n * 100 + t];
            s += g_nodeout[(size_t)(n + 1) * 100 + t];
            s += g_nodeout[(size_t)(n + 2) * 100 + t];
            s += g_nodeout[(size_t)(n + 3) * 100 + t];
        }
        for (; n < hi; n++) s += g_nodeout[(size_t)n * 100 + t];
        out[b * 100 + t] = s;
    }
}

// =====================================================================
extern "C" void kernel_launch(void* const* d_in, const int* in_sizes, int n_in,
                              void* d_out, int out_size)
{
    const float* X    = (const float*)d_in[0];   // walk_feats (8192,10)
    const float* hop1 = (const float*)d_in[1];
    const float* hop2 = (const float*)d_in[2];
    const float* hop3 = (const float*)d_in[3];
    const int*   bidx = (const int*)d_in[4];
    const float* W1   = (const float*)d_in[5];   // (4,10,100)
    const float* b1   = (const float*)d_in[6];   // (4,100)
    const float* W2   = (const float*)d_in[7];   // (4,100,100)
    const float* b2   = (const float*)d_in[8];   // (4,100)
    float* out = (float*)d_out;                  // (256,100)

    (void)in_sizes; (void)n_in; (void)out_size;

    cudaFuncSetAttribute(hop_gemv_kernel, cudaFuncAttributeMaxDynamicSharedMemorySize, SMEM_A_BYTES);
    cudaFuncSetAttribute(mlp_kernel,      cudaFuncAttributeMaxDynamicSharedMemorySize, SMEM_MLP_BYTES);

    hop_gemv_kernel<<<3072, 256, SMEM_A_BYTES>>>(hop1, hop2, hop3, X);
    mlp_kernel<<<256, 256, SMEM_MLP_BYTES>>>(X, W1, b1, W2, b2);
    segpool_kernel<<<NB_SEG, 128>>>(bidx, out);
}

// round 9
// speedup vs baseline: 1.2489x; 1.0343x over previous
#include <cuda_runtime.h>
#include <cstdint>
#include <cstddef>

#define NN 8192
#define RWD 10
#define HD1 100
#define HD2 100
#define NB_SEG 256

#define MSPLIT 16
#define MW 64                       // m-window per stage
#define ROWSB 128                   // rows per block (32 lanes x 4)
#define ITERS ((NN / MSPLIT) / MW)  // 8
#define HOP_TILE_BYTES (ROWSB * MW * 4)   // 32768
#define X_TILE_BYTES (MW * RWD * 4)       // 2560
// double-buffered: 2 x (32768 + 2560) = 70656 -> 3 blocks/SM
#define SMEM_A_BYTES (2 * (HOP_TILE_BYTES + X_TILE_BYTES))

typedef unsigned long long u64;

// ---------------- scratch (static device arrays; no allocation) ----------------
__device__ float g_part[3 * MSPLIT * NN * RWD];  // per-m-split partials of hopX
__device__ float g_nodeout[NN * HD2];            // per-node summed MLP output

// ---------------- helpers ----------------
__device__ __forceinline__ void fma2(u64 &acc, u64 a, u64 b) {
    asm("fma.rn.f32x2 %0, %1, %2, %0;" : "+l"(acc) : "l"(a), "l"(b));
}
__device__ __forceinline__ u64 pack2(float x, float y) {
    u64 r; asm("mov.b64 %0, {%1, %2};" : "=l"(r) : "f"(x), "f"(y)); return r;
}
__device__ __forceinline__ float2 unpack2(u64 v) {
    float2 r; asm("mov.b64 {%0, %1}, %2;" : "=f"(r.x), "=f"(r.y) : "l"(v)); return r;
}
__device__ __forceinline__ void cp_async16(uint32_t dst, const void* src) {
    asm volatile("cp.async.cg.shared.global [%0], [%1], 16;" :: "r"(dst), "l"(src));
}
__device__ __forceinline__ void cp_commit() { asm volatile("cp.async.commit_group;"); }
template<int N> __device__ __forceinline__ void cp_wait() {
    asm volatile("cp.async.wait_group %0;" :: "n"(N));
}

// =====================================================================
// Kernel A: partial hopX over this block's m-range (512 m of one hop).
// Now double-buffered, 3 blocks/SM (24 warps) for cross-block overlap.
// =====================================================================
extern "C" __global__ void __launch_bounds__(256, 3)
hop_gemv_kernel(const float* __restrict__ hop0, const float* __restrict__ hop1,
                const float* __restrict__ hop2, const float* __restrict__ X)
{
    extern __shared__ char smem[];
    char* hop_s = smem;                                   // 2 x 32KB
    char* x_s   = smem + 2 * HOP_TILE_BYTES;              // 2 x 2.5KB

    const int b   = blockIdx.x;                  // 3072 blocks
    const int k   = b >> 10;                     // 0..2
    const int rem = b & 1023;
    const int rg  = rem >> 4;                    // row group 0..63
    const int sp  = rem & 15;                    // m split 0..15
    const int row0   = rg * ROWSB;
    const int m_base = sp * (NN / MSPLIT);
    const float* hop = (k == 0) ? hop0 : (k == 1) ? hop1 : hop2;

    const int t = threadIdx.x;
    const int w = t >> 5, l = t & 31;

    const int tr = t >> 4;                    // 0..15
    const int tc = t & 15;                    // float4 column 0..15
    const int slotS = tc ^ (tr & 7);
    const char* gsrc0 = (const char*)(hop + (size_t)(row0 + tr) * NN + m_base + tc * 4);
    const uint32_t hdst0 = (uint32_t)__cvta_generic_to_shared(hop_s)
                         + (uint32_t)((tr * 16 + slotS) * 16);
    const char* xsrc0 = (const char*)(X + (size_t)m_base * RWD);
    const uint32_t xdst0 = (uint32_t)__cvta_generic_to_shared(x_s) + (uint32_t)(t * 16);

    auto stage = [&](int buf, int it) {
        const char* gs = gsrc0 + (size_t)it * (MW * 4);
        uint32_t hd = hdst0 + buf * HOP_TILE_BYTES;
        #pragma unroll
        for (int i = 0; i < 8; i++)
            cp_async16(hd + i * 4096, gs + (size_t)i * (16 * NN * 4));
        if (t < 160)
            cp_async16(xdst0 + buf * X_TILE_BYTES, xsrc0 + (size_t)it * X_TILE_BYTES + t * 16);
        cp_commit();
    };

    u64 acc[4][5];
    #pragma unroll
    for (int g = 0; g < 4; g++)
        #pragma unroll
        for (int p = 0; p < 5; p++) acc[p < 0 ? 0 : g][p] = 0ull;

    stage(0, 0);

    #pragma unroll 1
    for (int it = 0; it < ITERS; it++) {
        // restage into the other buffer (freed by trailing sync of prev iter)
        if (it + 1 < ITERS) { stage((it + 1) & 1, it + 1); cp_wait<1>(); }
        else                cp_wait<0>();
        __syncthreads();                    // buffer it visible to all warps

        const float4* hb = (const float4*)(hop_s + (it & 1) * HOP_TILE_BYTES);
        const u64*    xb = (const u64*)(x_s + (it & 1) * X_TILE_BYTES);

        #pragma unroll
        for (int q = 0; q < 2; q++) {
            const int c4   = (w << 1) + q;          // 0..15
            const int slot = c4 ^ (l & 7);
            float4 h4[4];
            #pragma unroll
            for (int g = 0; g < 4; g++)
                h4[g] = hb[((l + (g << 5)) << 4) + slot];
            const u64* xp = xb + c4 * 20;
            #pragma unroll
            for (int j = 0; j < 4; j++) {
                const float* hv0 = (const float*)&h4[0];
                const float* hv1 = (const float*)&h4[1];
                const float* hv2 = (const float*)&h4[2];
                const float* hv3 = (const float*)&h4[3];
                u64 A0 = pack2(hv0[j], hv0[j]);
                u64 A1 = pack2(hv1[j], hv1[j]);
                u64 A2 = pack2(hv2[j], hv2[j]);
                u64 A3 = pack2(hv3[j], hv3[j]);
                #pragma unroll
                for (int p = 0; p < 5; p++) {
                    u64 xv = xp[j * 5 + p];
                    fma2(acc[0][p], A0, xv);
                    fma2(acc[1][p], A1, xv);
                    fma2(acc[2][p], A2, xv);
                    fma2(acc[3][p], A3, xv);
                }
            }
        }
        __syncthreads();                    // all warps done -> buffer free
    }

    float* red = (float*)smem;
    #pragma unroll
    for (int g = 0; g < 4; g++) {
        int row = l + (g << 5);
        #pragma unroll
        for (int p = 0; p < 5; p++) {
            float2 v = unpack2(acc[g][p]);
            red[(w * ROWSB + row) * RWD + 2 * p]     = v.x;
            red[(w * ROWSB + row) * RWD + 2 * p + 1] = v.y;
        }
    }
    __syncthreads();
    for (int f = t; f < ROWSB * RWD; f += 256) {
        int row = f / RWD, d = f % RWD;
        float s = 0.f;
        #pragma unroll
        for (int ww = 0; ww < 8; ww++) s += red[(ww * ROWSB + row) * RWD + d];
        g_part[((size_t)(k * MSPLIT + sp) * NN + row0 + row) * RWD + d] = s;
    }
}

// =====================================================================
// Kernel B: node-parallel MLP, 256 blocks x 32 nodes.
// Phase 1: warp = 4 nodes, lane<25 = j-quad; W1 read once per lane as
//   ulonglong2 pairs, reused across 4 nodes; h stored duplicated (STS.128).
// Phase 2: 4 warps x 8 nodes, lane<25 = o-quad; W2 natural [d][o] layout,
//   cp.async double-buffered; no horizontal add; STG.128 output.
// =====================================================================
#define W2S_BYTES 40000
#define SMEM_H_OFF   80000
#define SMEM_INP_OFF 105600
#define SMEM_B2_OFF  106880
#define SMEM_MLP_BYTES 107392

extern "C" __global__ void __launch_bounds__(256, 2)
mlp_kernel(const float* __restrict__ X, const float* __restrict__ W1,
           const float* __restrict__ b1, const float* __restrict__ W2,
           const float* __restrict__ b2)
{
    extern __shared__ char smemb[];
    u64*   hsm2 = (u64*)(smemb + SMEM_H_OFF);     // [32][100] (h,h) pairs
    float* inp  = (float*)(smemb + SMEM_INP_OFF); // [320]
    float* b2s  = (float*)(smemb + SMEM_B2_OFF);  // [100]

    const int t = threadIdx.x;
    const int w = t >> 5, l = t & 31;
    const int node0 = blockIdx.x * 32;

    const uint32_t w2base = (uint32_t)__cvta_generic_to_shared(smemb);

    auto stageW2 = [&](int buf, int k) {
        const float4* src = (const float4*)(W2 + k * 10000);  // 2500 x 16B
        uint32_t dst = w2base + buf * W2S_BYTES;
        #pragma unroll
        for (int i = 0; i < 9; i++)
            cp_async16(dst + (i * 256 + t) * 16, src + i * 256 + t);
        if (t < 196)
            cp_async16(dst + (2304 + t) * 16, src + 2304 + t);
        cp_commit();
    };

    if (t < 100) b2s[t] = b2[t] + b2[100 + t] + b2[200 + t] + b2[300 + t];

    stageW2(0, 0);
    stageW2(1, 1);

    u64 acc[8][2];
    #pragma unroll
    for (int nn = 0; nn < 8; nn++) { acc[nn][0] = 0ull; acc[nn][1] = 0ull; }

    #pragma unroll 1
    for (int k = 0; k < 4; k++) {
        // ---- input tile for this k ----
        if (k == 0) {
            for (int f = t; f < 320; f += 256) inp[f] = X[(size_t)node0 * RWD + f];
        } else {
            const float* base = g_part + ((size_t)(k - 1) * MSPLIT * NN + node0) * RWD;
            for (int f = t; f < 320; f += 256) {
                float s = 0.f;
                #pragma unroll
                for (int sp = 0; sp < MSPLIT; sp++)
                    s += base[(size_t)sp * NN * RWD + f];
                inp[f] = s;
            }
        }
        if (k < 3) cp_wait<1>(); else cp_wait<0>();
        __syncthreads();   // weights(k) + inp visible; hsm2 free

        // ---- phase 1: warp = 4 nodes, lane<25 = j-quad ----
        if (l < 25) {
            const float* w1k = W1 + k * 1000;
            ulonglong2 w1p[10];
            #pragma unroll
            for (int r = 0; r < 10; r++)
                w1p[r] = *(const ulonglong2*)(w1k + r * 100 + 4 * l);
            float4 b1q = *(const float4*)(b1 + k * 100 + 4 * l);
            u64 binit0 = pack2(b1q.x, b1q.y), binit1 = pack2(b1q.z, b1q.w);
            #pragma unroll
            for (int nn = 0; nn < 4; nn++) {
                const int row = w * 4 + nn;
                u64 xp2[10];
                #pragma unroll
                for (int r = 0; r < 10; r++) {
                    float xv = inp[row * 10 + r];   // broadcast
                    xp2[r] = pack2(xv, xv);
                }
                u64 s0 = binit0, s1 = binit1;
                #pragma unroll
                for (int r = 0; r < 10; r++) {
                    fma2(s0, xp2[r], w1p[r].x);
                    fma2(s1, xp2[r], w1p[r].y);
                }
                float2 a = unpack2(s0), bb = unpack2(s1);
                float h0 = fmaxf(a.x, 0.f), h1 = fmaxf(a.y, 0.f);
                float h2 = fmaxf(bb.x, 0.f), h3 = fmaxf(bb.y, 0.f);
                ulonglong2 o01 = { pack2(h0, h0), pack2(h1, h1) };
                ulonglong2 o23 = { pack2(h2, h2), pack2(h3, h3) };
                *(ulonglong2*)&hsm2[row * 100 + 4 * l]     = o01;
                *(ulonglong2*)&hsm2[row * 100 + 4 * l + 2] = o23;
            }
        }
        __syncthreads();

        // ---- phase 2: warps 0-3, 8 nodes each; lane<25 = o-quad ----
        if (w < 4 && l < 25) {
            const float* w2f = (const float*)(smemb + (k & 1) * W2S_BYTES);
            #pragma unroll 5
            for (int d4 = 0; d4 < 25; d4++) {
                u64 wq[4][2];
                #pragma unroll
                for (int j = 0; j < 4; j++) {
                    ulonglong2 ww = *(const ulonglong2*)&w2f[(4 * d4 + j) * 100 + 4 * l];
                    wq[j][0] = ww.x; wq[j][1] = ww.y;
                }
                #pragma unroll
                for (int nn = 0; nn < 8; nn++) {
                    const int row = w * 8 + nn;
                    ulonglong2 h01 = *(const ulonglong2*)&hsm2[row * 100 + 4 * d4];
                    ulonglong2 h23 = *(const ulonglong2*)&hsm2[row * 100 + 4 * d4 + 2];
                    fma2(acc[nn][0], h01.x, wq[0][0]); fma2(acc[nn][1], h01.x, wq[0][1]);
                    fma2(acc[nn][0], h01.y, wq[1][0]); fma2(acc[nn][1], h01.y, wq[1][1]);
                    fma2(acc[nn][0], h23.x, wq[2][0]); fma2(acc[nn][1], h23.x, wq[2][1]);
                    fma2(acc[nn][0], h23.y, wq[3][0]); fma2(acc[nn][1], h23.y, wq[3][1]);
                }
            }
        }
        __syncthreads();   // w2 buffer (k&1) free for restage
        if (k + 2 < 4) stageW2(k & 1, k + 2);
    }

    // ---- output: node_out = acc + sum_k b2 ----
    if (w < 4 && l < 25) {
        float4 bv = *(const float4*)&b2s[4 * l];
        #pragma unroll
        for (int nn = 0; nn < 8; nn++) {
            int n = node0 + w * 8 + nn;
            float2 a0 = unpack2(acc[nn][0]);
            float2 a1 = unpack2(acc[nn][1]);
            float4 o4 = { a0.x + bv.x, a0.y + bv.y, a1.x + bv.z, a1.y + bv.w };
            *(float4*)&g_nodeout[(size_t)n * 100 + 4 * l] = o4;
        }
    }
}

// =====================================================================
// Kernel C: deterministic segment sum via binary search on sorted batch_idx
// =====================================================================
__device__ __forceinline__ int lbound(const int* a, int n, int v) {
    int lo = 0, hi = n;
    while (lo < hi) { int mid = (lo + hi) >> 1; if (a[mid] < v) lo = mid + 1; else hi = mid; }
    return lo;
}

extern "C" __global__ void segpool_kernel(const int* __restrict__ bidx,
                                          float* __restrict__ out)
{
    const int b = blockIdx.x;
    const int lo = lbound(bidx, NN, b);
    const int hi = lbound(bidx, NN, b + 1);
    const int t = threadIdx.x;
    if (t < 100) {
        float s = 0.f;
        int n = lo;
        for (; n + 3 < hi; n += 4) {
            s += g_nodeout[(size_t)n * 100 + t];
            s += g_nodeout[(size_t)(n + 1) * 100 + t];
            s += g_nodeout[(size_t)(n + 2) * 100 + t];
            s += g_nodeout[(size_t)(n + 3) * 100 + t];
        }
        for (; n < hi; n++) s += g_nodeout[(size_t)n * 100 + t];
        out[b * 100 + t] = s;
    }
}

// =====================================================================
extern "C" void kernel_launch(void* const* d_in, const int* in_sizes, int n_in,
                              void* d_out, int out_size)
{
    const float* X    = (const float*)d_in[0];   // walk_feats (8192,10)
    const float* hop1 = (const float*)d_in[1];
    const float* hop2 = (const float*)d_in[2];
    const float* hop3 = (const float*)d_in[3];
    const int*   bidx = (const int*)d_in[4];
    const float* W1   = (const float*)d_in[5];   // (4,10,100)
    const float* b1   = (const float*)d_in[6];   // (4,100)
    const float* W2   = (const float*)d_in[7];   // (4,100,100)
    const float* b2   = (const float*)d_in[8];   // (4,100)
    float* out = (float*)d_out;                  // (256,100)

    (void)in_sizes; (void)n_in; (void)out_size;

    cudaFuncSetAttribute(hop_gemv_kernel, cudaFuncAttributeMaxDynamicSharedMemorySize, SMEM_A_BYTES);
    cudaFuncSetAttribute(mlp_kernel,      cudaFuncAttributeMaxDynamicSharedMemorySize, SMEM_MLP_BYTES);

    hop_gemv_kernel<<<3072, 256, SMEM_A_BYTES>>>(hop1, hop2, hop3, X);
    mlp_kernel<<<256, 256, SMEM_MLP_BYTES>>>(X, W1, b1, W2, b2);
    segpool_kernel<<<NB_SEG, 128>>>(bidx, out);
}

// round 10
// speedup vs baseline: 1.2818x; 1.0264x over previous
#include <cuda_runtime.h>
#include <cstdint>
#include <cstddef>

#define NN 8192
#define RWD 10
#define HD1 100
#define HD2 100
#define NB_SEG 256

#define MSPLIT 16
#define MW 64                       // m-window per stage
#define ROWSB 128                   // rows per block (32 lanes x 4)
#define ITERS ((NN / MSPLIT) / MW)  // 8
#define HOP_TILE_BYTES (ROWSB * MW * 4)   // 32768
#define X_TILE_BYTES (MW * RWD * 4)       // 2560
// triple-buffered: depth-2 prefetch (proven best in R8)
#define SMEM_A_BYTES (3 * (HOP_TILE_BYTES + X_TILE_BYTES))  // 105984 -> 2 blocks/SM

typedef unsigned long long u64;

// ---------------- scratch (static device arrays; no allocation) ----------------
__device__ float g_part[3 * MSPLIT * NN * RWD];  // per-m-split partials of hopX
__device__ float g_nodeout[NN * HD2];            // per-node summed MLP output

// ---------------- helpers ----------------
__device__ __forceinline__ void fma2(u64 &acc, u64 a, u64 b) {
    asm("fma.rn.f32x2 %0, %1, %2, %0;" : "+l"(acc) : "l"(a), "l"(b));
}
__device__ __forceinline__ u64 pack2(float x, float y) {
    u64 r; asm("mov.b64 %0, {%1, %2};" : "=l"(r) : "f"(x), "f"(y)); return r;
}
__device__ __forceinline__ float2 unpack2(u64 v) {
    float2 r; asm("mov.b64 {%0, %1}, %2;" : "=f"(r.x), "=f"(r.y) : "l"(v)); return r;
}
__device__ __forceinline__ void cp_async16(uint32_t dst, const void* src) {
    asm volatile("cp.async.cg.shared.global [%0], [%1], 16;" :: "r"(dst), "l"(src));
}
__device__ __forceinline__ void cp_commit() { asm volatile("cp.async.commit_group;"); }
template<int N> __device__ __forceinline__ void cp_wait() {
    asm volatile("cp.async.wait_group %0;" :: "n"(N));
}

// =====================================================================
// Kernel A: partial hopX over this block's m-range (512 m of one hop).
// R8 configuration (best measured: 126.1us, 82.3% DRAM): triple-buffered
// cp.async (depth-2 prefetch), 2 blocks/SM.
// =====================================================================
extern "C" __global__ void __launch_bounds__(256, 2)
hop_gemv_kernel(const float* __restrict__ hop0, const float* __restrict__ hop1,
                const float* __restrict__ hop2, const float* __restrict__ X)
{
    extern __shared__ char smem[];
    char* hop_s = smem;                                   // 3 x 32KB
    char* x_s   = smem + 3 * HOP_TILE_BYTES;              // 3 x 2.5KB

    const int b   = blockIdx.x;                  // 3072 blocks
    const int k   = b >> 10;                     // 0..2
    const int rem = b & 1023;
    const int rg  = rem >> 4;                    // row group 0..63
    const int sp  = rem & 15;                    // m split 0..15
    const int row0   = rg * ROWSB;
    const int m_base = sp * (NN / MSPLIT);
    const float* hop = (k == 0) ? hop0 : (k == 1) ? hop1 : hop2;

    const int t = threadIdx.x;
    const int w = t >> 5, l = t & 31;

    const int tr = t >> 4;                    // 0..15
    const int tc = t & 15;                    // float4 column 0..15
    const int slotS = tc ^ (tr & 7);
    const char* gsrc0 = (const char*)(hop + (size_t)(row0 + tr) * NN + m_base + tc * 4);
    const uint32_t hdst0 = (uint32_t)__cvta_generic_to_shared(hop_s)
                         + (uint32_t)((tr * 16 + slotS) * 16);
    const char* xsrc0 = (const char*)(X + (size_t)m_base * RWD);
    const uint32_t xdst0 = (uint32_t)__cvta_generic_to_shared(x_s) + (uint32_t)(t * 16);

    auto stage = [&](int buf, int it) {
        const char* gs = gsrc0 + (size_t)it * (MW * 4);
        uint32_t hd = hdst0 + buf * HOP_TILE_BYTES;
        #pragma unroll
        for (int i = 0; i < 8; i++)
            cp_async16(hd + i * 4096, gs + (size_t)i * (16 * NN * 4));
        if (t < 160)
            cp_async16(xdst0 + buf * X_TILE_BYTES, xsrc0 + (size_t)it * X_TILE_BYTES + t * 16);
        cp_commit();
    };

    u64 acc[4][5];
    #pragma unroll
    for (int g = 0; g < 4; g++)
        #pragma unroll
        for (int p = 0; p < 5; p++) acc[g][p] = 0ull;

    stage(0, 0);
    stage(1, 1);

    int bc = 2;
    #pragma unroll 1
    for (int it = 0; it < ITERS; it++) {
        __syncthreads();                    // compute(it-1) done -> buffer free
        if (it + 2 < ITERS) {
            stage(bc, it + 2);
            bc = (bc == 2) ? 0 : bc + 1;
            cp_wait<2>();
        } else if (it + 1 < ITERS) cp_wait<1>();
        else                       cp_wait<0>();
        __syncthreads();                    // buffer it visible to all warps

        const float4* hb = (const float4*)(hop_s + (it % 3) * HOP_TILE_BYTES);
        const u64*    xb = (const u64*)(x_s + (it % 3) * X_TILE_BYTES);

        #pragma unroll
        for (int q = 0; q < 2; q++) {
            const int c4   = (w << 1) + q;          // 0..15
            const int slot = c4 ^ (l & 7);
            float4 h4[4];
            #pragma unroll
            for (int g = 0; g < 4; g++)
                h4[g] = hb[((l + (g << 5)) << 4) + slot];
            const u64* xp = xb + c4 * 20;
            #pragma unroll
            for (int j = 0; j < 4; j++) {
                const float* hv0 = (const float*)&h4[0];
                const float* hv1 = (const float*)&h4[1];
                const float* hv2 = (const float*)&h4[2];
                const float* hv3 = (const float*)&h4[3];
                u64 A0 = pack2(hv0[j], hv0[j]);
                u64 A1 = pack2(hv1[j], hv1[j]);
                u64 A2 = pack2(hv2[j], hv2[j]);
                u64 A3 = pack2(hv3[j], hv3[j]);
                #pragma unroll
                for (int p = 0; p < 5; p++) {
                    u64 xv = xp[j * 5 + p];
                    fma2(acc[0][p], A0, xv);
                    fma2(acc[1][p], A1, xv);
                    fma2(acc[2][p], A2, xv);
                    fma2(acc[3][p], A3, xv);
                }
            }
        }
    }

    float* red = (float*)smem;
    __syncthreads();
    #pragma unroll
    for (int g = 0; g < 4; g++) {
        int row = l + (g << 5);
        #pragma unroll
        for (int p = 0; p < 5; p++) {
            float2 v = unpack2(acc[g][p]);
            red[(w * ROWSB + row) * RWD + 2 * p]     = v.x;
            red[(w * ROWSB + row) * RWD + 2 * p + 1] = v.y;
        }
    }
    __syncthreads();
    for (int f = t; f < ROWSB * RWD; f += 256) {
        int row = f / RWD, d = f % RWD;
        float s = 0.f;
        #pragma unroll
        for (int ww = 0; ww < 8; ww++) s += red[(ww * ROWSB + row) * RWD + d];
        g_part[((size_t)(k * MSPLIT + sp) * NN + row0 + row) * RWD + d] = s;
    }
}

// =====================================================================
// Kernel B: node-parallel MLP, 256 blocks x 32 nodes.  (R9 version, keep)
// Phase 1: warp = 4 nodes, lane<25 = j-quad; W1 read once per lane as
//   ulonglong2 pairs, reused across 4 nodes; h stored duplicated (STS.128).
// Phase 2: 4 warps x 8 nodes, lane<25 = o-quad; W2 natural [d][o] layout,
//   cp.async double-buffered; no horizontal add; STG.128 output.
// =====================================================================
#define W2S_BYTES 40000
#define SMEM_H_OFF   80000
#define SMEM_INP_OFF 105600
#define SMEM_B2_OFF  106880
#define SMEM_MLP_BYTES 107392

extern "C" __global__ void __launch_bounds__(256, 2)
mlp_kernel(const float* __restrict__ X, const float* __restrict__ W1,
           const float* __restrict__ b1, const float* __restrict__ W2,
           const float* __restrict__ b2)
{
    extern __shared__ char smemb[];
    u64*   hsm2 = (u64*)(smemb + SMEM_H_OFF);     // [32][100] (h,h) pairs
    float* inp  = (float*)(smemb + SMEM_INP_OFF); // [320]
    float* b2s  = (float*)(smemb + SMEM_B2_OFF);  // [100]

    const int t = threadIdx.x;
    const int w = t >> 5, l = t & 31;
    const int node0 = blockIdx.x * 32;

    const uint32_t w2base = (uint32_t)__cvta_generic_to_shared(smemb);

    auto stageW2 = [&](int buf, int k) {
        const float4* src = (const float4*)(W2 + k * 10000);  // 2500 x 16B
        uint32_t dst = w2base + buf * W2S_BYTES;
        #pragma unroll
        for (int i = 0; i < 9; i++)
            cp_async16(dst + (i * 256 + t) * 16, src + i * 256 + t);
        if (t < 196)
            cp_async16(dst + (2304 + t) * 16, src + 2304 + t);
        cp_commit();
    };

    if (t < 100) b2s[t] = b2[t] + b2[100 + t] + b2[200 + t] + b2[300 + t];

    stageW2(0, 0);
    stageW2(1, 1);

    u64 acc[8][2];
    #pragma unroll
    for (int nn = 0; nn < 8; nn++) { acc[nn][0] = 0ull; acc[nn][1] = 0ull; }

    #pragma unroll 1
    for (int k = 0; k < 4; k++) {
        // ---- input tile for this k ----
        if (k == 0) {
            for (int f = t; f < 320; f += 256) inp[f] = X[(size_t)node0 * RWD + f];
        } else {
            const float* base = g_part + ((size_t)(k - 1) * MSPLIT * NN + node0) * RWD;
            for (int f = t; f < 320; f += 256) {
                float s = 0.f;
                #pragma unroll
                for (int sp = 0; sp < MSPLIT; sp++)
                    s += base[(size_t)sp * NN * RWD + f];
                inp[f] = s;
            }
        }
        if (k < 3) cp_wait<1>(); else cp_wait<0>();
        __syncthreads();   // weights(k) + inp visible; hsm2 free

        // ---- phase 1: warp = 4 nodes, lane<25 = j-quad ----
        if (l < 25) {
            const float* w1k = W1 + k * 1000;
            ulonglong2 w1p[10];
            #pragma unroll
            for (int r = 0; r < 10; r++)
                w1p[r] = *(const ulonglong2*)(w1k + r * 100 + 4 * l);
            float4 b1q = *(const float4*)(b1 + k * 100 + 4 * l);
            u64 binit0 = pack2(b1q.x, b1q.y), binit1 = pack2(b1q.z, b1q.w);
            #pragma unroll
            for (int nn = 0; nn < 4; nn++) {
                const int row = w * 4 + nn;
                u64 xp2[10];
                #pragma unroll
                for (int r = 0; r < 10; r++) {
                    float xv = inp[row * 10 + r];   // broadcast
                    xp2[r] = pack2(xv, xv);
                }
                u64 s0 = binit0, s1 = binit1;
                #pragma unroll
                for (int r = 0; r < 10; r++) {
                    fma2(s0, xp2[r], w1p[r].x);
                    fma2(s1, xp2[r], w1p[r].y);
                }
                float2 a = unpack2(s0), bb = unpack2(s1);
                float h0 = fmaxf(a.x, 0.f), h1 = fmaxf(a.y, 0.f);
                float h2 = fmaxf(bb.x, 0.f), h3 = fmaxf(bb.y, 0.f);
                ulonglong2 o01 = { pack2(h0, h0), pack2(h1, h1) };
                ulonglong2 o23 = { pack2(h2, h2), pack2(h3, h3) };
                *(ulonglong2*)&hsm2[row * 100 + 4 * l]     = o01;
                *(ulonglong2*)&hsm2[row * 100 + 4 * l + 2] = o23;
            }
        }
        __syncthreads();

        // ---- phase 2: warps 0-3, 8 nodes each; lane<25 = o-quad ----
        if (w < 4 && l < 25) {
            const float* w2f = (const float*)(smemb + (k & 1) * W2S_BYTES);
            #pragma unroll 5
            for (int d4 = 0; d4 < 25; d4++) {
                u64 wq[4][2];
                #pragma unroll
                for (int j = 0; j < 4; j++) {
                    ulonglong2 ww = *(const ulonglong2*)&w2f[(4 * d4 + j) * 100 + 4 * l];
                    wq[j][0] = ww.x; wq[j][1] = ww.y;
                }
                #pragma unroll
                for (int nn = 0; nn < 8; nn++) {
                    const int row = w * 8 + nn;
                    ulonglong2 h01 = *(const ulonglong2*)&hsm2[row * 100 + 4 * d4];
                    ulonglong2 h23 = *(const ulonglong2*)&hsm2[row * 100 + 4 * d4 + 2];
                    fma2(acc[nn][0], h01.x, wq[0][0]); fma2(acc[nn][1], h01.x, wq[0][1]);
                    fma2(acc[nn][0], h01.y, wq[1][0]); fma2(acc[nn][1], h01.y, wq[1][1]);
                    fma2(acc[nn][0], h23.x, wq[2][0]); fma2(acc[nn][1], h23.x, wq[2][1]);
                    fma2(acc[nn][0], h23.y, wq[3][0]); fma2(acc[nn][1], h23.y, wq[3][1]);
                }
            }
        }
        __syncthreads();   // w2 buffer (k&1) free for restage
        if (k + 2 < 4) stageW2(k & 1, k + 2);
    }

    // ---- output: node_out = acc + sum_k b2 ----
    if (w < 4 && l < 25) {
        float4 bv = *(const float4*)&b2s[4 * l];
        #pragma unroll
        for (int nn = 0; nn < 8; nn++) {
            int n = node0 + w * 8 + nn;
            float2 a0 = unpack2(acc[nn][0]);
            float2 a1 = unpack2(acc[nn][1]);
            float4 o4 = { a0.x + bv.x, a0.y + bv.y, a1.x + bv.z, a1.y + bv.w };
            *(float4*)&g_nodeout[(size_t)n * 100 + 4 * l] = o4;
        }
    }
}

// =====================================================================
// Kernel C: deterministic segment sum via binary search on sorted batch_idx
// =====================================================================
__device__ __forceinline__ int lbound(const int* a, int n, int v) {
    int lo = 0, hi = n;
    while (lo < hi) { int mid = (lo + hi) >> 1; if (a[mid] < v) lo = mid + 1; else hi = mid; }
    return lo;
}

extern "C" __global__ void segpool_kernel(const int* __restrict__ bidx,
                                          float* __restrict__ out)
{
    const int b = blockIdx.x;
    const int lo = lbound(bidx, NN, b);
    const int hi = lbound(bidx, NN, b + 1);
    const int t = threadIdx.x;
    if (t < 100) {
        float s = 0.f;
        int n = lo;
        for (; n + 3 < hi; n += 4) {
            s += g_nodeout[(size_t)n * 100 + t];
            s += g_nodeout[(size_t)(n + 1) * 100 + t];
            s += g_nodeout[(size_t)(n + 2) * 100 + t];
            s += g_nodeout[(size_t)(n + 3) * 100 + t];
        }
        for (; n < hi; n++) s += g_nodeout[(size_t)n * 100 + t];
        out[b * 100 + t] = s;
    }
}

// =====================================================================
extern "C" void kernel_launch(void* const* d_in, const int* in_sizes, int n_in,
                              void* d_out, int out_size)
{
    const float* X    = (const float*)d_in[0];   // walk_feats (8192,10)
    const float* hop1 = (const float*)d_in[1];
    const float* hop2 = (const float*)d_in[2];
    const float* hop3 = (const float*)d_in[3];
    const int*   bidx = (const int*)d_in[4];
    const float* W1   = (const float*)d_in[5];   // (4,10,100)
    const float* b1   = (const float*)d_in[6];   // (4,100)
    const float* W2   = (const float*)d_in[7];   // (4,100,100)
    const float* b2   = (const float*)d_in[8];   // (4,100)
    float* out = (float*)d_out;                  // (256,100)

    (void)in_sizes; (void)n_in; (void)out_size;

    cudaFuncSetAttribute(hop_gemv_kernel, cudaFuncAttributeMaxDynamicSharedMemorySize, SMEM_A_BYTES);
    cudaFuncSetAttribute(mlp_kernel,      cudaFuncAttributeMaxDynamicSharedMemorySize, SMEM_MLP_BYTES);

    hop_gemv_kernel<<<3072, 256, SMEM_A_BYTES>>>(hop1, hop2, hop3, X);
    mlp_kernel<<<256, 256, SMEM_MLP_BYTES>>>(X, W1, b1, W2, b2);
    segpool_kernel<<<NB_SEG, 128>>>(bidx, out);
}